// round 12
// baseline (speedup 1.0000x reference)
#include <cuda_runtime.h>
#include <math.h>

#define N_NODES 50000
#define N_ENV   1000000
#define N_EDGES 200000
#define NDD     512              // D * N_AXIS = 64*8
#define NODE_OUT_ELEMS (N_NODES * NDD)

// Scratch
__device__ float g_summ[N_NODES * 192];      // aggr (mean), written by reduce kernel
__device__ int   g_counts[N_NODES];
__device__ int   g_start[N_NODES];
__device__ int   g_cursor[N_NODES];
__device__ int   g_pos[N_ENV];               // sorted slot of env e
__device__ float g_vs[(long long)N_ENV * 3]; // env vectors in sorted order
__device__ float g_o[(long long)N_ENV * 64]; // per-env MLP output, sorted order (256MB)

typedef unsigned long long u64;
typedef unsigned int u32;

__device__ __forceinline__ u64 pack2(float lo, float hi) {
    u64 r; asm("mov.b64 %0, {%1,%2};" : "=l"(r) : "f"(lo), "f"(hi)); return r;
}
__device__ __forceinline__ void unpack2(u64 v, float& lo, float& hi) {
    asm("mov.b64 {%0,%1}, %2;" : "=f"(lo), "=f"(hi) : "l"(v));
}
__device__ __forceinline__ u64 fma2(u64 a, u64 b, u64 c) {
    u64 d; asm("fma.rn.f32x2 %0, %1, %2, %3;" : "=l"(d) : "l"(a), "l"(b), "l"(c)); return d;
}
__device__ __forceinline__ float tanh_fast(float x) {
    float y; asm("tanh.approx.f32 %0, %1;" : "=f"(y) : "f"(x)); return y;
}
__device__ __forceinline__ u32 to_tf32(float x) {
    u32 u; asm("cvt.rna.tf32.f32 %0, %1;" : "=r"(u) : "f"(x)); return u;
}
__device__ __forceinline__ void st_cs_v2(float* p, float a, float b) {
    asm volatile("st.global.cs.v2.f32 [%0], {%1,%2};" :: "l"(p), "f"(a), "f"(b) : "memory");
}
__device__ __forceinline__ void st_cs_v4(float* p, float4 v) {
    asm volatile("st.global.cs.v4.f32 [%0], {%1,%2,%3,%4};"
                 :: "l"(p), "f"(v.x), "f"(v.y), "f"(v.z), "f"(v.w) : "memory");
}
// D/C frag: c0=(row=gid,col=2tg) c1=(gid,2tg+1) c2=(gid+8,2tg) c3=(gid+8,2tg+1)
__device__ __forceinline__ void mma_tf32(float* d, u32 a0, u32 a1, u32 a2, u32 a3,
                                         u32 b0, u32 b1) {
    asm volatile(
        "mma.sync.aligned.m16n8k8.row.col.f32.tf32.tf32.f32 "
        "{%0,%1,%2,%3},{%4,%5,%6,%7},{%8,%9},{%0,%1,%2,%3};"
        : "+f"(d[0]), "+f"(d[1]), "+f"(d[2]), "+f"(d[3])
        : "r"(a0), "r"(a1), "r"(a2), "r"(a3), "r"(b0), "r"(b1));
}

// ============ sort machinery ============

__global__ void zero_counts_kernel() {
    int i = blockIdx.x * blockDim.x + threadIdx.x;
    if (i < N_NODES) g_counts[i] = 0;
}

__global__ void hist_kernel(const int* __restrict__ env_index) {
    int e = blockIdx.x * blockDim.x + threadIdx.x;
    if (e < N_ENV) atomicAdd(&g_counts[env_index[N_ENV + e]], 1);
}

// single-block exclusive scan over 50000 counts
__global__ void scan_kernel() {
    const int T = 1024, CH = (N_NODES + T - 1) / T;   // 49
    __shared__ int ssum[T];
    int t = threadIdx.x;
    int lo = t * CH, hi = min(lo + CH, N_NODES);
    int local = 0;
    for (int i = lo; i < hi; i++) local += g_counts[i];
    ssum[t] = local;
    __syncthreads();
    int acc = local;
    for (int off = 1; off < T; off *= 2) {
        int v = (t >= off) ? ssum[t - off] : 0;
        __syncthreads();
        ssum[t] += v;
        __syncthreads();
    }
    int run = ssum[t] - acc;
    for (int i = lo; i < hi; i++) {
        g_start[i] = run;
        g_cursor[i] = run;
        run += g_counts[i];
    }
}

// assigns sorted slot to each env (coalesced reads); also deposits the env
// vector into the sorted-order g_vs so the reduce kernel never gathers.
__global__ void scatter_kernel(const int* __restrict__ env_index,
                               const float* __restrict__ env_vectors) {
    int e = blockIdx.x * blockDim.x + threadIdx.x;
    if (e < N_ENV) {
        int pos = atomicAdd(&g_cursor[env_index[N_ENV + e]], 1);
        g_pos[e] = pos;
        float vx = env_vectors[3 * e + 0];
        float vy = env_vectors[3 * e + 1];
        float vz = env_vectors[3 * e + 2];
        g_vs[(long long)pos * 3 + 0] = vx;
        g_vs[(long long)pos * 3 + 1] = vy;
        g_vs[(long long)pos * 3 + 2] = vz;
    }
}

// ============ env MLP (ORIGINAL order -> coalesced loads; scattered row store) ============

#define OFF_W1 0                 // 288
#define OFF_B1 288               // 32
#define OFF_B2 320               // 64
#define OFF_B3 384               // 64
#define OFF_W2 448               // 32 x 72 tf32
#define OFF_W3 2752              // 64 x 72 tf32
#define OFF_H  7360              // 8 warps x [32][68]  (slot 64 of each row holds pos bits)
#define SMEM_FLOATS (7360 + 8 * 32 * 68)   // 99072 B
#define N_WARPS_TOTAL (N_ENV / 32)         // 31250

__global__ void __launch_bounds__(256, 2) env_kernel(
    const float* __restrict__ env_vectors,
    const float* __restrict__ atom_attr,
    const int*   __restrict__ env_index,
    const float* __restrict__ W1, const float* __restrict__ b1,
    const float* __restrict__ W2, const float* __restrict__ b2,
    const float* __restrict__ W3, const float* __restrict__ b3)
{
    extern __shared__ __align__(16) float sm[];
    int tid = threadIdx.x;

    for (int i = tid; i < 288; i += 256) sm[OFF_W1 + i] = W1[i];
    for (int i = tid; i < 32;  i += 256) sm[OFF_B1 + i] = b1[i];
    for (int i = tid; i < 64;  i += 256) sm[OFF_B2 + i] = b2[i];
    for (int i = tid; i < 64;  i += 256) sm[OFF_B3 + i] = b3[i];
    for (int i = tid; i < 2048; i += 256) {
        int k = i >> 6, n = i & 63;
        sm[OFF_W2 + k * 72 + n] = __uint_as_float(to_tf32(W2[i]));
    }
    for (int i = tid; i < 4096; i += 256) {
        int k = i >> 6, n = i & 63;
        sm[OFF_W3 + k * 72 + n] = __uint_as_float(to_tf32(W3[i]));
    }
    __syncthreads();

    int wid  = tid >> 5;
    int lane = tid & 31;
    int warpg = blockIdx.x * 8 + wid;
    if (warpg >= N_WARPS_TOTAL) return;
    int e_base = warpg * 32;

    float* H = &sm[OFF_H + wid * (32 * 68)];
    const float* sW1 = &sm[OFF_W1];
    const float* sb1 = &sm[OFF_B1];

    // ---- layer 1 (exact fp32), lane = env (sequential, coalesced) ----
    {
        int e = e_base + lane;
        float vx = env_vectors[3 * e + 0];
        float vy = env_vectors[3 * e + 1];
        float vz = env_vectors[3 * e + 2];
        float r = sqrtf(vx * vx + vy * vy + vz * vz);
        float inv_r = 1.0f / r;
        float snorm;
        if (r < 3.0f) snorm = inv_r;
        else if (r < 6.0f) {
            float u = (r - 6.0f) * (-1.0f / 3.0f);
            snorm = inv_r * (u * u * u * (10.0f + u * (-15.0f + 6.0f * u)) + 1.0f);
        } else snorm = 0.0f;

        int i0 = env_index[e];
        int i1 = env_index[N_ENV + e];
        float4 a0 = *(const float4*)&atom_attr[4 * i0];
        float4 a1 = *(const float4*)&atom_attr[4 * i1];

        u64 inp[9];
        inp[0] = pack2(snorm, snorm);
        inp[1] = pack2(a0.x, a0.x); inp[2] = pack2(a0.y, a0.y);
        inp[3] = pack2(a0.z, a0.z); inp[4] = pack2(a0.w, a0.w);
        inp[5] = pack2(a1.x, a1.x); inp[6] = pack2(a1.y, a1.y);
        inp[7] = pack2(a1.z, a1.z); inp[8] = pack2(a1.w, a1.w);

        float h1[32];
#pragma unroll
        for (int j = 0; j < 32; j += 4) {
            ulonglong2 b = *(const ulonglong2*)&sb1[j];
            u64 s0 = b.x, s1 = b.y;
#pragma unroll
            for (int i = 0; i < 9; i++) {
                ulonglong2 w = *(const ulonglong2*)&sW1[i * 32 + j];
                s0 = fma2(inp[i], w.x, s0);
                s1 = fma2(inp[i], w.y, s1);
            }
            float x0, x1, x2, x3;
            unpack2(s0, x0, x1); unpack2(s1, x2, x3);
            h1[j + 0] = tanh_fast(x0);
            h1[j + 1] = tanh_fast(x1);
            h1[j + 2] = tanh_fast(x2);
            h1[j + 3] = tanh_fast(x3);
        }
#pragma unroll
        for (int k = 0; k < 32; k += 2)
            *(float2*)&H[lane * 68 + k] = make_float2(h1[k], h1[k + 1]);
        // stash this env's sorted slot in the spare smem slot of its row
        H[lane * 68 + 64] = __int_as_float(g_pos[e]);
    }
    __syncwarp();

    int gid = lane >> 2;
    int tg  = lane & 3;
    const float* sW2 = &sm[OFF_W2];
    const float* sW3 = &sm[OFF_W3];
    const float* sb2 = &sm[OFF_B2];
    const float* sb3 = &sm[OFF_B3];

    for (int m = 0; m < 2; m++) {
        int rA = (m * 16 + gid) * 68;
        int rB = (m * 16 + gid + 8) * 68;

        // ---- layer 2: K=32 ----
        float h2[8][4];
#pragma unroll
        for (int nt = 0; nt < 8; nt++) {
            float bb0 = sb2[nt * 8 + tg * 2], bb1 = sb2[nt * 8 + tg * 2 + 1];
            h2[nt][0] = bb0; h2[nt][1] = bb1; h2[nt][2] = bb0; h2[nt][3] = bb1;
        }
#pragma unroll
        for (int kt = 0; kt < 4; kt++) {
            u32 fa0 = to_tf32(H[rA + kt * 8 + tg]);
            u32 fa1 = to_tf32(H[rB + kt * 8 + tg]);
            u32 fa2 = to_tf32(H[rA + kt * 8 + tg + 4]);
            u32 fa3 = to_tf32(H[rB + kt * 8 + tg + 4]);
#pragma unroll
            for (int nt = 0; nt < 8; nt++) {
                u32 fb0 = __float_as_uint(sW2[(kt * 8 + tg) * 72 + nt * 8 + gid]);
                u32 fb1 = __float_as_uint(sW2[(kt * 8 + tg + 4) * 72 + nt * 8 + gid]);
                mma_tf32(h2[nt], fa0, fa1, fa2, fa3, fb0, fb1);
            }
        }
#pragma unroll
        for (int nt = 0; nt < 8; nt++) {
            h2[nt][0] = tanh_fast(h2[nt][0]);
            h2[nt][1] = tanh_fast(h2[nt][1]);
            h2[nt][2] = tanh_fast(h2[nt][2]);
            h2[nt][3] = tanh_fast(h2[nt][3]);
        }
        __syncwarp();
#pragma unroll
        for (int nt = 0; nt < 8; nt++) {
            *(float2*)&H[rA + nt * 8 + tg * 2] = make_float2(h2[nt][0], h2[nt][1]);
            *(float2*)&H[rB + nt * 8 + tg * 2] = make_float2(h2[nt][2], h2[nt][3]);
        }
        __syncwarp();

        // ---- layer 3: K=64 ----
        float d3[8][4];
#pragma unroll
        for (int nt = 0; nt < 8; nt++) {
            float bb0 = sb3[nt * 8 + tg * 2], bb1 = sb3[nt * 8 + tg * 2 + 1];
            d3[nt][0] = bb0; d3[nt][1] = bb1; d3[nt][2] = bb0; d3[nt][3] = bb1;
        }
#pragma unroll
        for (int kt = 0; kt < 8; kt++) {
            u32 fa0 = to_tf32(H[rA + kt * 8 + tg]);
            u32 fa1 = to_tf32(H[rB + kt * 8 + tg]);
            u32 fa2 = to_tf32(H[rA + kt * 8 + tg + 4]);
            u32 fa3 = to_tf32(H[rB + kt * 8 + tg + 4]);
#pragma unroll
            for (int nt = 0; nt < 8; nt++) {
                u32 fb0 = __float_as_uint(sW3[(kt * 8 + tg) * 72 + nt * 8 + gid]);
                u32 fb1 = __float_as_uint(sW3[(kt * 8 + tg + 4) * 72 + nt * 8 + gid]);
                mma_tf32(d3[nt], fa0, fa1, fa2, fa3, fb0, fb1);
            }
        }

        // ---- epilogue: tanh + residual -> scatter o rows to sorted slots ----
        long long posA = __float_as_int(H[rA + 64]);
        long long posB = __float_as_int(H[rB + 64]);
        float* oA = &g_o[posA * 64];
        float* oB = &g_o[posB * 64];
#pragma unroll
        for (int nt = 0; nt < 8; nt++) {
            int off = nt * 8 + tg * 2;
            st_cs_v2(oA + off, tanh_fast(d3[nt][0]) + h2[nt][0],
                               tanh_fast(d3[nt][1]) + h2[nt][1]);
            st_cs_v2(oB + off, tanh_fast(d3[nt][2]) + h2[nt][2],
                               tanh_fast(d3[nt][3]) + h2[nt][3]);
        }
    }
}

// ============ per-node gather-reduce + self-outer ============
// 4 nodes per 256-thread block; 64 threads per node (thread = dim d).
// All reads contiguous: o rows and v rows are both in sorted order.
__global__ void __launch_bounds__(256) reduce_node_kernel(float* __restrict__ out)
{
    int t = threadIdx.x;
    int local = t >> 6;
    int d = t & 63;
    int n = blockIdx.x * 4 + local;

    __shared__ float sA[4][3][8];

    int start = g_start[n];
    int count = g_counts[n];

    float s0 = 0.f, s1 = 0.f, s2 = 0.f;
    for (int q = 0; q < count; q++) {
        long long pos = start + q;
        float o = g_o[pos * 64 + d];
        float vx = g_vs[pos * 3 + 0];
        float vy = g_vs[pos * 3 + 1];
        float vz = g_vs[pos * 3 + 2];
        s0 = fmaf(o, vx, s0);
        s1 = fmaf(o, vy, s1);
        s2 = fmaf(o, vz, s2);
    }
    float inv = 1.0f / fmaxf((float)count, 1.0f);
    float c0 = s0 * inv, c1 = s1 * inv, c2 = s2 * inv;

    float* base = &g_summ[(long long)n * 192];
    base[  0 + d] = c0;
    base[ 64 + d] = c1;
    base[128 + d] = c2;

    if (d < 8) {
        sA[local][0][d] = c0;
        sA[local][1][d] = c1;
        sA[local][2][d] = c2;
    }
    __syncthreads();

    float res[8];
#pragma unroll
    for (int a = 0; a < 8; a++)
        res[a] = c0 * sA[local][0][a] + c1 * sA[local][1][a] + c2 * sA[local][2][a];

    float4* op = (float4*)&out[(long long)n * NDD + d * 8];
    op[0] = make_float4(res[0], res[1], res[2], res[3]);
    op[1] = make_float4(res[4], res[5], res[6], res[7]);
}

// ============ edge kernel (recompute from aggr) ============
__global__ void __launch_bounds__(256) edge_kernel(
    const int* __restrict__ edge_index,
    float* __restrict__ out)
{
    int t = threadIdx.x;
    int g = t >> 6;
    int d = t & 63;
    int k = blockIdx.x * 4 + g;

    __shared__ float sA[4][2][3][8];

    int i = edge_index[k];
    int j = edge_index[N_EDGES + k];
    const float* Ai = &g_summ[(long long)i * 192];
    const float* Aj = &g_summ[(long long)j * 192];
    float ai0 = Ai[d], ai1 = Ai[64 + d], ai2 = Ai[128 + d];
    float aj0 = Aj[d], aj1 = Aj[64 + d], aj2 = Aj[128 + d];

    if (d < 8) {
        sA[g][0][0][d] = ai0; sA[g][0][1][d] = ai1; sA[g][0][2][d] = ai2;
        sA[g][1][0][d] = aj0; sA[g][1][1][d] = aj1; sA[g][1][2][d] = aj2;
    }
    __syncthreads();

    float res[8];
#pragma unroll
    for (int a = 0; a < 8; a++) {
        res[a] = ai0 * sA[g][0][0][a] + ai1 * sA[g][0][1][a] + ai2 * sA[g][0][2][a]
               + aj0 * sA[g][1][0][a] + aj1 * sA[g][1][1][a] + aj2 * sA[g][1][2][a];
    }

    float* op = &out[(long long)k * NDD + d * 8];
    st_cs_v4(op,     make_float4(res[0], res[1], res[2], res[3]));
    st_cs_v4(op + 4, make_float4(res[4], res[5], res[6], res[7]));
}

extern "C" void kernel_launch(void* const* d_in, const int* in_sizes, int n_in,
                              void* d_out, int out_size)
{
    const float* env_vectors = (const float*)d_in[0];
    const float* atom_attr   = (const float*)d_in[1];
    const int*   env_index   = (const int*)  d_in[2];
    const int*   edge_index  = (const int*)  d_in[3];
    const float* W1 = (const float*)d_in[4];
    const float* b1 = (const float*)d_in[5];
    const float* W2 = (const float*)d_in[6];
    const float* b2 = (const float*)d_in[7];
    const float* W3 = (const float*)d_in[8];
    const float* b3 = (const float*)d_in[9];

    float* out = (float*)d_out;
    float* node_out = out;                       // [50000, 512]
    float* edge_out = out + NODE_OUT_ELEMS;      // [200000, 512]

    size_t smem_bytes = SMEM_FLOATS * sizeof(float);   // 99072
    cudaFuncSetAttribute(env_kernel, cudaFuncAttributeMaxDynamicSharedMemorySize,
                         (int)smem_bytes);

    zero_counts_kernel<<<(N_NODES + 255) / 256, 256>>>();
    hist_kernel<<<(N_ENV + 255) / 256, 256>>>(env_index);
    scan_kernel<<<1, 1024>>>();
    scatter_kernel<<<(N_ENV + 255) / 256, 256>>>(env_index, env_vectors);
    env_kernel<<<(N_WARPS_TOTAL + 7) / 8, 256, smem_bytes>>>(
        env_vectors, atom_attr, env_index, W1, b1, W2, b2, W3, b3);
    reduce_node_kernel<<<N_NODES / 4, 256>>>(node_out);
    edge_kernel<<<N_EDGES / 4, 256>>>(edge_index, edge_out);
}

// round 13
// speedup vs baseline: 1.3382x; 1.3382x over previous
#include <cuda_runtime.h>
#include <cuda_fp16.h>
#include <math.h>

#define N_NODES 50000
#define N_ENV   1000000
#define N_EDGES 200000
#define NDD     512              // D * N_AXIS = 64*8
#define NODE_OUT_ELEMS (N_NODES * NDD)

// Scratch: per-node accumulators. Layout: [node][3][64] (component-major).
// After node_kernel this holds the MEAN (aggr) in place.
__device__ float g_summ[N_NODES * 192];
__device__ float g_cnt[N_NODES];

typedef unsigned long long u64;
typedef unsigned int u32;

__device__ __forceinline__ u64 pack2(float lo, float hi) {
    u64 r; asm("mov.b64 %0, {%1,%2};" : "=l"(r) : "f"(lo), "f"(hi)); return r;
}
__device__ __forceinline__ void unpack2(u64 v, float& lo, float& hi) {
    asm("mov.b64 {%0,%1}, %2;" : "=f"(lo), "=f"(hi) : "l"(v));
}
__device__ __forceinline__ u64 fma2(u64 a, u64 b, u64 c) {
    u64 d; asm("fma.rn.f32x2 %0, %1, %2, %3;" : "=l"(d) : "l"(a), "l"(b), "l"(c)); return d;
}
__device__ __forceinline__ float tanh_fast(float x) {
    float y; asm("tanh.approx.f32 %0, %1;" : "=f"(y) : "f"(x)); return y;
}
__device__ __forceinline__ u32 packh2(float a, float b) {
    __half2 h = __floats2half2_rn(a, b);
    return *reinterpret_cast<u32*>(&h);
}
__device__ __forceinline__ void red_add_v4(float* p, float a, float b, float c, float d) {
    asm volatile("red.global.add.v4.f32 [%0], {%1,%2,%3,%4};"
                 :: "l"(p), "f"(a), "f"(b), "f"(c), "f"(d) : "memory");
}
__device__ __forceinline__ void st_cs_v4(float* p, float4 v) {
    asm volatile("st.global.cs.v4.f32 [%0], {%1,%2,%3,%4};"
                 :: "l"(p), "f"(v.x), "f"(v.y), "f"(v.z), "f"(v.w) : "memory");
}
// mma.m16n8k8 f16 (f32 accum).
// D/C frag: c0=(row=gid,col=2tg) c1=(gid,2tg+1) c2=(gid+8,2tg) c3=(gid+8,2tg+1)
// A frag: a0={A[gid][8kt+2tg],A[gid][8kt+2tg+1]}  a1=same rows gid+8
// B frag (col): b0={B[8kt+2tg][n=gid],B[8kt+2tg+1][n=gid]}
__device__ __forceinline__ void mma_f16(float* d, u32 a0, u32 a1, u32 b0) {
    asm volatile(
        "mma.sync.aligned.m16n8k8.row.col.f32.f16.f16.f32 "
        "{%0,%1,%2,%3},{%4,%5},{%6},{%0,%1,%2,%3};"
        : "+f"(d[0]), "+f"(d[1]), "+f"(d[2]), "+f"(d[3])
        : "r"(a0), "r"(a1), "r"(b0));
}

__global__ void zero_kernel() {
    int i = blockIdx.x * blockDim.x + threadIdx.x;
    int stride = gridDim.x * blockDim.x;
    float4* p = (float4*)g_summ;
    const float4 z = make_float4(0.f, 0.f, 0.f, 0.f);
    for (int k = i; k < N_NODES * 48; k += stride) p[k] = z;
    for (int k = i; k < N_NODES; k += stride) g_cnt[k] = 0.f;
}

// Shared memory word map (u32 units):
#define OFF_W1  0        // 288 f32
#define OFF_B1  288      // 32 f32
#define OFF_B2  320      // 64 f32
#define OFF_B3  384      // 64 f32
#define OFF_W2H 448      // 64 n x 20 words (f16x2 pairs along k; 16 used)
#define OFF_W3H 1728     // 64 n x 36 words (32 used)
#define OFF_H   4032     // per warp: H1 32 rows x 20 words, then H2 16 rows x 36 words
#define WARP_H_WORDS (32 * 20 + 16 * 36)   // 1216
#define SMEM_WORDS (OFF_H + 8 * WARP_H_WORDS)  // 13760 words = 55040 B
#define N_WARPS_TOTAL (N_ENV / 32)         // 31250

__global__ void __launch_bounds__(256, 3) env_kernel(
    const float* __restrict__ env_vectors,
    const float* __restrict__ atom_attr,
    const int*   __restrict__ env_index,
    const float* __restrict__ W1, const float* __restrict__ b1,
    const float* __restrict__ W2, const float* __restrict__ b2,
    const float* __restrict__ W3, const float* __restrict__ b3)
{
    extern __shared__ __align__(16) u32 smu[];
    float* smf = (float*)smu;
    int tid = threadIdx.x;

    // ---- stage weights ----
    for (int i = tid; i < 288; i += 256) smf[OFF_W1 + i] = W1[i];
    for (int i = tid; i < 32;  i += 256) smf[OFF_B1 + i] = b1[i];
    for (int i = tid; i < 64;  i += 256) smf[OFF_B2 + i] = b2[i];
    for (int i = tid; i < 64;  i += 256) smf[OFF_B3 + i] = b3[i];
    // W2 [32k x 64n] -> f16x2 pairs along k: word(n, kw) kw<16, stride 20
    for (int i = tid; i < 64 * 16; i += 256) {
        int n = i >> 4, kw = i & 15;
        smu[OFF_W2H + n * 20 + kw] = packh2(W2[(2 * kw) * 64 + n], W2[(2 * kw + 1) * 64 + n]);
    }
    // W3 [64k x 64n]: kw<32, stride 36
    for (int i = tid; i < 64 * 32; i += 256) {
        int n = i >> 5, kw = i & 31;
        smu[OFF_W3H + n * 36 + kw] = packh2(W3[(2 * kw) * 64 + n], W3[(2 * kw + 1) * 64 + n]);
    }
    __syncthreads();

    int wid  = tid >> 5;
    int lane = tid & 31;
    int warpg = blockIdx.x * 8 + wid;
    if (warpg >= N_WARPS_TOTAL) return;
    int e_base = warpg * 32;

    u32* H1 = &smu[OFF_H + wid * WARP_H_WORDS];          // 32 rows x 20
    u32* H2 = H1 + 32 * 20;                              // 16 rows x 36
    const float* sW1 = &smf[OFF_W1];
    const float* sb1 = &smf[OFF_B1];
    const float* sb2 = &smf[OFF_B2];
    const float* sb3 = &smf[OFF_B3];

    // ================= scalar layer 1 (exact fp32), lane = env =================
    {
        int e = e_base + lane;
        float vx = env_vectors[3 * e + 0];
        float vy = env_vectors[3 * e + 1];
        float vz = env_vectors[3 * e + 2];
        float r = sqrtf(vx * vx + vy * vy + vz * vz);
        float inv_r = 1.0f / r;
        float snorm;
        if (r < 3.0f) snorm = inv_r;
        else if (r < 6.0f) {
            float u = (r - 6.0f) * (-1.0f / 3.0f);
            snorm = inv_r * (u * u * u * (10.0f + u * (-15.0f + 6.0f * u)) + 1.0f);
        } else snorm = 0.0f;

        int i0 = env_index[e];
        int i1 = env_index[N_ENV + e];
        float4 a0 = *(const float4*)&atom_attr[4 * i0];
        float4 a1 = *(const float4*)&atom_attr[4 * i1];

        u64 inp[9];
        inp[0] = pack2(snorm, snorm);
        inp[1] = pack2(a0.x, a0.x); inp[2] = pack2(a0.y, a0.y);
        inp[3] = pack2(a0.z, a0.z); inp[4] = pack2(a0.w, a0.w);
        inp[5] = pack2(a1.x, a1.x); inp[6] = pack2(a1.y, a1.y);
        inp[7] = pack2(a1.z, a1.z); inp[8] = pack2(a1.w, a1.w);

        float h1[32];
#pragma unroll
        for (int j = 0; j < 32; j += 4) {
            ulonglong2 b = *(const ulonglong2*)&sb1[j];
            u64 s0 = b.x, s1 = b.y;
#pragma unroll
            for (int i = 0; i < 9; i++) {
                ulonglong2 w = *(const ulonglong2*)&sW1[i * 32 + j];
                s0 = fma2(inp[i], w.x, s0);
                s1 = fma2(inp[i], w.y, s1);
            }
            float x0, x1, x2, x3;
            unpack2(s0, x0, x1); unpack2(s1, x2, x3);
            h1[j + 0] = tanh_fast(x0);
            h1[j + 1] = tanh_fast(x1);
            h1[j + 2] = tanh_fast(x2);
            h1[j + 3] = tanh_fast(x3);
        }
        // stage h1 as f16x2 pairs: row=lane, 16 words, stride 20
#pragma unroll
        for (int k = 0; k < 16; k++)
            H1[lane * 20 + k] = packh2(h1[2 * k], h1[2 * k + 1]);
    }
    __syncwarp();

    int gid = lane >> 2;       // 0..7
    int tg  = lane & 3;        // 0..3
    const u32* W2u = &smu[OFF_W2H];
    const u32* W3u = &smu[OFF_W3H];

    for (int m = 0; m < 2; m++) {
        int r1A = (m * 16 + gid) * 20;
        int r1B = (m * 16 + gid + 8) * 20;

        // ---- layer 2: K=32 (4 k-steps), all 8 nt ----
        float h2r[8][4];
#pragma unroll
        for (int nt = 0; nt < 8; nt++) {
            float bb0 = sb2[nt * 8 + tg * 2], bb1 = sb2[nt * 8 + tg * 2 + 1];
            h2r[nt][0] = bb0; h2r[nt][1] = bb1; h2r[nt][2] = bb0; h2r[nt][3] = bb1;
        }
#pragma unroll
        for (int kt = 0; kt < 4; kt++) {
            u32 a0 = H1[r1A + 4 * kt + tg];
            u32 a1 = H1[r1B + 4 * kt + tg];
#pragma unroll
            for (int nt = 0; nt < 8; nt++) {
                u32 b = W2u[(nt * 8 + gid) * 20 + 4 * kt + tg];
                mma_f16(h2r[nt], a0, a1, b);
            }
        }
#pragma unroll
        for (int nt = 0; nt < 8; nt++) {
            h2r[nt][0] = tanh_fast(h2r[nt][0]);
            h2r[nt][1] = tanh_fast(h2r[nt][1]);
            h2r[nt][2] = tanh_fast(h2r[nt][2]);
            h2r[nt][3] = tanh_fast(h2r[nt][3]);
        }
        __syncwarp();   // previous m's layer-3 reads of H2 are done
#pragma unroll
        for (int nt = 0; nt < 8; nt++) {
            H2[gid * 36 + nt * 4 + tg]       = packh2(h2r[nt][0], h2r[nt][1]);
            H2[(gid + 8) * 36 + nt * 4 + tg] = packh2(h2r[nt][2], h2r[nt][3]);
        }
        __syncwarp();

        // per-m epilogue context
        int eA = e_base + m * 16 + gid;
        int eB = eA + 8;
        int odd = tg & 1;
        int e_use = odd ? eB : eA;
        float vx = env_vectors[3 * e_use + 0];
        float vy = env_vectors[3 * e_use + 1];
        float vz = env_vectors[3 * e_use + 2];
        int n_use = env_index[N_ENV + e_use];
        float* base = &g_summ[(long long)n_use * 192];
        int col4 = (tg & 2) * 2;

        // ---- layer 3: K=64 (8 k-steps), 2 passes of 4 nt ----
#pragma unroll
        for (int np = 0; np < 2; np++) {
            float d3[4][4];
#pragma unroll
            for (int j = 0; j < 4; j++) {
                int nt = np * 4 + j;
                float bb0 = sb3[nt * 8 + tg * 2], bb1 = sb3[nt * 8 + tg * 2 + 1];
                d3[j][0] = bb0; d3[j][1] = bb1; d3[j][2] = bb0; d3[j][3] = bb1;
            }
#pragma unroll
            for (int kt = 0; kt < 8; kt++) {
                u32 a0 = H2[gid * 36 + 4 * kt + tg];
                u32 a1 = H2[(gid + 8) * 36 + 4 * kt + tg];
#pragma unroll
                for (int j = 0; j < 4; j++) {
                    u32 b = W3u[((np * 4 + j) * 8 + gid) * 36 + 4 * kt + tg];
                    mma_f16(d3[j], a0, a1, b);
                }
            }
            // tanh + residual, pair-shuffle to 4-wide, red.v4 scatter
#pragma unroll
            for (int j = 0; j < 4; j++) {
                int nt = np * 4 + j;
                float oA0 = tanh_fast(d3[j][0]) + h2r[nt][0];
                float oA1 = tanh_fast(d3[j][1]) + h2r[nt][1];
                float oB0 = tanh_fast(d3[j][2]) + h2r[nt][2];
                float oB1 = tanh_fast(d3[j][3]) + h2r[nt][3];
                float pA0 = __shfl_xor_sync(0xffffffff, oA0, 1);
                float pA1 = __shfl_xor_sync(0xffffffff, oA1, 1);
                float pB0 = __shfl_xor_sync(0xffffffff, oB0, 1);
                float pB1 = __shfl_xor_sync(0xffffffff, oB1, 1);
                float q0 = odd ? pB0 : oA0;
                float q1 = odd ? pB1 : oA1;
                float q2 = odd ? oB0 : pA0;
                float q3 = odd ? oB1 : pA1;
                int off = nt * 8 + col4;
                red_add_v4(base +   0 + off, q0 * vx, q1 * vx, q2 * vx, q3 * vx);
                red_add_v4(base +  64 + off, q0 * vy, q1 * vy, q2 * vy, q3 * vy);
                red_add_v4(base + 128 + off, q0 * vz, q1 * vz, q2 * vz, q3 * vz);
            }
        }
        if (tg == 0) {
            atomicAdd(&g_cnt[env_index[N_ENV + eA]], 1.0f);
            atomicAdd(&g_cnt[env_index[N_ENV + eB]], 1.0f);
        }
    }
}

// 4 nodes per 256-thread block. Computes aggr (mean), writes node_desc, AND
// writes aggr back into g_summ in place for the edge kernel to reuse.
__global__ void __launch_bounds__(256) node_kernel(float* __restrict__ out)
{
    int t = threadIdx.x;
    int local = t >> 6;
    int d = t & 63;
    int n = blockIdx.x * 4 + local;

    __shared__ float sA[4][3][8];

    float cnt = g_cnt[n];
    float inv = 1.0f / fmaxf(cnt, 1.0f);
    float* base = &g_summ[(long long)n * 192];
    float c0 = base[  0 + d] * inv;
    float c1 = base[ 64 + d] * inv;
    float c2 = base[128 + d] * inv;

    if (d < 8) {
        sA[local][0][d] = c0;
        sA[local][1][d] = c1;
        sA[local][2][d] = c2;
    }
    base[  0 + d] = c0;
    base[ 64 + d] = c1;
    base[128 + d] = c2;
    __syncthreads();

    float res[8];
#pragma unroll
    for (int a = 0; a < 8; a++)
        res[a] = c0 * sA[local][0][a] + c1 * sA[local][1][a] + c2 * sA[local][2][a];

    float4* op = (float4*)&out[(long long)n * NDD + d * 8];
    op[0] = make_float4(res[0], res[1], res[2], res[3]);
    op[1] = make_float4(res[4], res[5], res[6], res[7]);
}

// 4 edges per 256-thread block; recompute both endpoint descriptors from the
// small (38MB, L2-resident) aggr buffer instead of gathering 2KB node_desc rows.
__global__ void __launch_bounds__(256) edge_kernel(
    const int* __restrict__ edge_index,
    float* __restrict__ out)
{
    int t = threadIdx.x;
    int g = t >> 6;
    int d = t & 63;
    int k = blockIdx.x * 4 + g;

    __shared__ float sA[4][2][3][8];

    int i = edge_index[k];
    int j = edge_index[N_EDGES + k];
    const float* Ai = &g_summ[(long long)i * 192];
    const float* Aj = &g_summ[(long long)j * 192];
    float ai0 = Ai[d], ai1 = Ai[64 + d], ai2 = Ai[128 + d];
    float aj0 = Aj[d], aj1 = Aj[64 + d], aj2 = Aj[128 + d];

    if (d < 8) {
        sA[g][0][0][d] = ai0; sA[g][0][1][d] = ai1; sA[g][0][2][d] = ai2;
        sA[g][1][0][d] = aj0; sA[g][1][1][d] = aj1; sA[g][1][2][d] = aj2;
    }
    __syncthreads();

    float res[8];
#pragma unroll
    for (int a = 0; a < 8; a++) {
        res[a] = ai0 * sA[g][0][0][a] + ai1 * sA[g][0][1][a] + ai2 * sA[g][0][2][a]
               + aj0 * sA[g][1][0][a] + aj1 * sA[g][1][1][a] + aj2 * sA[g][1][2][a];
    }

    float* op = &out[(long long)k * NDD + d * 8];
    st_cs_v4(op,     make_float4(res[0], res[1], res[2], res[3]));
    st_cs_v4(op + 4, make_float4(res[4], res[5], res[6], res[7]));
}

extern "C" void kernel_launch(void* const* d_in, const int* in_sizes, int n_in,
                              void* d_out, int out_size)
{
    const float* env_vectors = (const float*)d_in[0];
    const float* atom_attr   = (const float*)d_in[1];
    const int*   env_index   = (const int*)  d_in[2];
    const int*   edge_index  = (const int*)  d_in[3];
    const float* W1 = (const float*)d_in[4];
    const float* b1 = (const float*)d_in[5];
    const float* W2 = (const float*)d_in[6];
    const float* b2 = (const float*)d_in[7];
    const float* W3 = (const float*)d_in[8];
    const float* b3 = (const float*)d_in[9];

    float* out = (float*)d_out;
    float* node_out = out;                       // [50000, 512]
    float* edge_out = out + NODE_OUT_ELEMS;      // [200000, 512]

    size_t smem_bytes = SMEM_WORDS * sizeof(u32);   // 55040
    cudaFuncSetAttribute(env_kernel, cudaFuncAttributeMaxDynamicSharedMemorySize,
                         (int)smem_bytes);

    zero_kernel<<<2048, 256>>>();
    env_kernel<<<(N_WARPS_TOTAL + 7) / 8, 256, smem_bytes>>>(
        env_vectors, atom_attr, env_index, W1, b1, W2, b2, W3, b3);
    node_kernel<<<N_NODES / 4, 256>>>(node_out);
    edge_kernel<<<N_EDGES / 4, 256>>>(edge_index, edge_out);
}